// round 9
// baseline (speedup 1.0000x reference)
#include <cuda_runtime.h>
#include <cuda_fp16.h>

#define N_NODES 100000
#define N_EDGES 1600000
#define F_HID 64
#define NCHUNK ((N_NODES + 1023) / 1024)
#define NPART 12500                       // agg1 grid (= N_NODES/8 warps)
#define FULLM 0xffffffffu

#define PACK2(dst, lo, hi) \
    asm("mov.b64 %0, {%1, %2};" : "=l"(dst) : "r"(__float_as_uint(lo)), "r"(__float_as_uint(hi)))
#define UNPACK2(lo, hi, src) \
    { unsigned int _l, _h; asm("mov.b64 {%0, %1}, %2;" : "=r"(_l), "=r"(_h) : "l"(src)); \
      lo = __uint_as_float(_l); hi = __uint_as_float(_h); }
#define FFMA2(acc, a, b) \
    asm("fma.rn.f32x2 %0, %1, %2, %0;" : "+l"(acc) : "l"(a), "l"(b))

// ---------------- scratch (static device globals) ----------------
__device__ int    g_is64;
__device__ int    g_cnt[N_NODES];
__device__ int    g_rowstart[N_NODES];
__device__ int    g_cursor[N_NODES];
__device__ int    g_col[N_EDGES];
__device__ int    g_bsum[NCHUNK];
__device__ float  g_dinv[N_NODES];
__device__ float  g_w[N_NODES];           // sum over out-edges of dinv[dst]
__device__ __half g_xsh[(size_t)N_NODES * F_HID];
__device__ float  g_v[F_HID];             // v = sum_j coef_j * h_j (atomics)

// ---------------- zero + dtype sniff (block 0) ----------------
__global__ void k_zero(const unsigned int* __restrict__ e) {
    int i = blockIdx.x * blockDim.x + threadIdx.x;
    if (i < N_NODES) { g_cnt[i] = 0; g_w[i] = 0.f; }
    if (i < F_HID)   g_v[i] = 0.f;
    if (blockIdx.x == 0 && threadIdx.x < 32) {
        unsigned int acc = 0;
        for (int k = threadIdx.x; k < 2048; k += 32)
            if (k & 1) acc |= e[k];
        #pragma unroll
        for (int o = 16; o; o >>= 1) acc |= __shfl_xor_sync(FULLM, acc, o);
        if (threadIdx.x == 0) g_is64 = (acc == 0u) ? 1 : 0;
    }
}

// ---------------- degree count over dst ----------------
__global__ void k_count(const void* __restrict__ eiv) {
    int e = blockIdx.x * blockDim.x + threadIdx.x;
    if (e >= N_EDGES) return;
    int d;
    if (g_is64) d = (int)((const long long*)eiv)[N_EDGES + e];
    else        d = ((const int*)eiv)[N_EDGES + e];
    atomicAdd(&g_cnt[d], 1);
}

// ---------------- exclusive scan ----------------
__global__ void k_scan_partial() {
    __shared__ int wsum[8];
    int t = threadIdx.x;
    int lane = t & 31, w = t >> 5;
    int gi = blockIdx.x * 256 + t;
    int4 v = make_int4(0, 0, 0, 0);
    if (gi < N_NODES / 4) v = ((const int4*)g_cnt)[gi];
    int p0 = v.x, p1 = p0 + v.y, p2 = p1 + v.z, p3 = p2 + v.w;
    int tsum = p3;
    int incl = tsum;
    #pragma unroll
    for (int o = 1; o < 32; o <<= 1) {
        int n = __shfl_up_sync(FULLM, incl, o);
        if (lane >= o) incl += n;
    }
    if (lane == 31) wsum[w] = incl;
    __syncthreads();
    if (w == 0) {
        int s = (lane < 8) ? wsum[lane] : 0;
        #pragma unroll
        for (int o = 1; o < 8; o <<= 1) {
            int n = __shfl_up_sync(FULLM, s, o);
            if (lane >= o) s += n;
        }
        if (lane < 8) wsum[lane] = s;
    }
    __syncthreads();
    int base = (w > 0 ? wsum[w - 1] : 0) + (incl - tsum);
    if (gi < N_NODES / 4)
        ((int4*)g_rowstart)[gi] = make_int4(base, base + p0, base + p1, base + p2);
    if (t == 0) g_bsum[blockIdx.x] = wsum[7];
}

__global__ void k_scan_bsum() {
    int lane = threadIdx.x;
    int carry = 0;
    for (int b = 0; b < NCHUNK; b += 32) {
        int i = b + lane;
        int v = (i < NCHUNK) ? g_bsum[i] : 0;
        int incl = v;
        #pragma unroll
        for (int o = 1; o < 32; o <<= 1) {
            int n = __shfl_up_sync(FULLM, incl, o);
            if (lane >= o) incl += n;
        }
        if (i < NCHUNK) g_bsum[i] = incl - v + carry;
        carry += __shfl_sync(FULLM, incl, 31);
    }
}

__global__ void k_scan_add() {
    int i = blockIdx.x * blockDim.x + threadIdx.x;
    if (i >= N_NODES) return;
    int rs = g_rowstart[i] + g_bsum[i >> 10];
    g_rowstart[i] = rs;
    g_cursor[i]   = rs;
    g_dinv[i] = rsqrtf((float)(g_cnt[i] + 1));
}

// ---------------- CSR placement + w scatter ----------------
__global__ void k_place(const void* __restrict__ eiv) {
    int e = blockIdx.x * blockDim.x + threadIdx.x;
    if (e >= N_EDGES) return;
    int s, d;
    if (g_is64) {
        s = (int)((const long long*)eiv)[e];
        d = (int)((const long long*)eiv)[N_EDGES + e];
    } else {
        s = ((const int*)eiv)[e];
        d = ((const int*)eiv)[N_EDGES + e];
    }
    int pos = atomicAdd(&g_cursor[d], 1);
    g_col[pos] = s;
    atomicAdd(&g_w[s], g_dinv[d]);
}

// ---------------- GEMM1: xsh = fp16(dinv*(x@W1)), FFMA2 path ------------
// tile 128 rows x 64 cols; thread: 4 rows x 8 cols (16 FFMA2 per k).
__global__ void __launch_bounds__(256) k_gemm1(const float* __restrict__ x,
                                               const float* __restrict__ W1) {
    __shared__ float Ws[64 * 64];          // [k][c]
    __shared__ float XsT[64][128];         // [k][row]  (transposed)
    int t = threadIdx.x;
    for (int i = t; i < 64 * 64; i += 256) Ws[i] = W1[i];
    int c8 = t & 7;            // cols 8*c8 .. 8*c8+7
    int r4 = t >> 3;           // rows 4*r4 .. 4*r4+3
    int ntiles = (N_NODES + 127) / 128;
    for (int tile = blockIdx.x; tile < ntiles; tile += gridDim.x) {
        int row0 = tile * 128;
        __syncthreads();
        for (int i = t; i < 128 * 16; i += 256) {
            int row = i & 127, kq = i >> 7;
            int grow = row0 + row;
            float4 v = make_float4(0.f, 0.f, 0.f, 0.f);
            if (grow < N_NODES) v = *(const float4*)(x + (size_t)grow * 64 + 4 * kq);
            XsT[4 * kq + 0][row] = v.x;
            XsT[4 * kq + 1][row] = v.y;
            XsT[4 * kq + 2][row] = v.z;
            XsT[4 * kq + 3][row] = v.w;
        }
        __syncthreads();
        unsigned long long acc[4][4] = {};   // [row][colpair]; bits 0 == (0.f,0.f)
        #pragma unroll
        for (int k = 0; k < 64; k++) {
            float4 av = *(const float4*)&XsT[k][4 * r4];
            ulonglong2 w01 = *(const ulonglong2*)&Ws[k * 64 + 8 * c8];
            ulonglong2 w23 = *(const ulonglong2*)&Ws[k * 64 + 8 * c8 + 4];
            unsigned long long a0, a1, a2, a3;
            PACK2(a0, av.x, av.x); PACK2(a1, av.y, av.y);
            PACK2(a2, av.z, av.z); PACK2(a3, av.w, av.w);
            FFMA2(acc[0][0], a0, w01.x); FFMA2(acc[0][1], a0, w01.y);
            FFMA2(acc[0][2], a0, w23.x); FFMA2(acc[0][3], a0, w23.y);
            FFMA2(acc[1][0], a1, w01.x); FFMA2(acc[1][1], a1, w01.y);
            FFMA2(acc[1][2], a1, w23.x); FFMA2(acc[1][3], a1, w23.y);
            FFMA2(acc[2][0], a2, w01.x); FFMA2(acc[2][1], a2, w01.y);
            FFMA2(acc[2][2], a2, w23.x); FFMA2(acc[2][3], a2, w23.y);
            FFMA2(acc[3][0], a3, w01.x); FFMA2(acc[3][1], a3, w01.y);
            FFMA2(acc[3][2], a3, w23.x); FFMA2(acc[3][3], a3, w23.y);
        }
        #pragma unroll
        for (int i = 0; i < 4; i++) {
            int grow = row0 + 4 * r4 + i;
            if (grow < N_NODES) {
                float d = g_dinv[grow];
                float lo, hi;
                UNPACK2(lo, hi, acc[i][0]);
                __half2 h0 = __floats2half2_rn(d * lo, d * hi);
                UNPACK2(lo, hi, acc[i][1]);
                __half2 h1 = __floats2half2_rn(d * lo, d * hi);
                UNPACK2(lo, hi, acc[i][2]);
                __half2 h2 = __floats2half2_rn(d * lo, d * hi);
                UNPACK2(lo, hi, acc[i][3]);
                __half2 h3 = __floats2half2_rn(d * lo, d * hi);
                uint4 o;
                o.x = *(unsigned int*)&h0; o.y = *(unsigned int*)&h1;
                o.z = *(unsigned int*)&h2; o.w = *(unsigned int*)&h3;
                *(uint4*)(g_xsh + (size_t)grow * 64 + 8 * c8) = o;
            }
        }
    }
}

// ---------------- fused agg1 + relu + weighted pool (atomic v) -----------
__global__ void __launch_bounds__(256) k_agg1(const float* __restrict__ b1) {
    __shared__ float sp[8][64];
    int t = threadIdx.x;
    int warp = t >> 5, lane = t & 31;
    int gw = blockIdx.x * 8 + warp;       // all gw < N_NODES
    const __half2* xs2 = (const __half2*)g_xsh;
    int start = g_rowstart[gw];
    int cnt   = g_cnt[gw];
    float2 self = __half22float2(xs2[(size_t)gw * 32 + lane]);
    float ax = self.x, ay = self.y;
    float bx = 0.f, by = 0.f;
    for (int base = 0; base < cnt; base += 32) {
        int idx = base + lane;
        int j = (idx < cnt) ? g_col[start + idx] : 0;
        int m = min(32, cnt - base);
        int k = 0;
        for (; k + 8 <= m; k += 8) {
            int j0 = __shfl_sync(FULLM, j, k);
            int j1 = __shfl_sync(FULLM, j, k + 1);
            int j2 = __shfl_sync(FULLM, j, k + 2);
            int j3 = __shfl_sync(FULLM, j, k + 3);
            int j4 = __shfl_sync(FULLM, j, k + 4);
            int j5 = __shfl_sync(FULLM, j, k + 5);
            int j6 = __shfl_sync(FULLM, j, k + 6);
            int j7 = __shfl_sync(FULLM, j, k + 7);
            float2 v0 = __half22float2(__ldg(&xs2[(size_t)j0 * 32 + lane]));
            float2 v1 = __half22float2(__ldg(&xs2[(size_t)j1 * 32 + lane]));
            float2 v2 = __half22float2(__ldg(&xs2[(size_t)j2 * 32 + lane]));
            float2 v3 = __half22float2(__ldg(&xs2[(size_t)j3 * 32 + lane]));
            float2 v4 = __half22float2(__ldg(&xs2[(size_t)j4 * 32 + lane]));
            float2 v5 = __half22float2(__ldg(&xs2[(size_t)j5 * 32 + lane]));
            float2 v6 = __half22float2(__ldg(&xs2[(size_t)j6 * 32 + lane]));
            float2 v7 = __half22float2(__ldg(&xs2[(size_t)j7 * 32 + lane]));
            ax += (v0.x + v1.x) + (v2.x + v3.x);
            bx += (v4.x + v5.x) + (v6.x + v7.x);
            ay += (v0.y + v1.y) + (v2.y + v3.y);
            by += (v4.y + v5.y) + (v6.y + v7.y);
        }
        for (; k + 2 <= m; k += 2) {
            int ja = __shfl_sync(FULLM, j, k);
            int jb = __shfl_sync(FULLM, j, k + 1);
            float2 va = __half22float2(__ldg(&xs2[(size_t)ja * 32 + lane]));
            float2 vb = __half22float2(__ldg(&xs2[(size_t)jb * 32 + lane]));
            ax += va.x + vb.x; ay += va.y + vb.y;
        }
        for (; k < m; k++) {
            int jj = __shfl_sync(FULLM, j, k);
            float2 v = __half22float2(__ldg(&xs2[(size_t)jj * 32 + lane]));
            ax += v.x; ay += v.y;
        }
    }
    ax += bx; ay += by;
    float di = g_dinv[gw];
    float h0 = fmaxf(fmaf(di, ax, b1[2 * lane]),     0.f);
    float h1 = fmaxf(fmaf(di, ay, b1[2 * lane + 1]), 0.f);
    float coef = di * (di + g_w[gw]);
    sp[warp][2 * lane]     = coef * h0;
    sp[warp][2 * lane + 1] = coef * h1;
    __syncthreads();
    if (t < 64) {
        float s = 0.f;
        #pragma unroll
        for (int w = 0; w < 8; w++) s += sp[w][t];
        atomicAdd(&g_v[t], s);
    }
}

// ---------------- final: pooled = v@W2/N + b2, log_softmax ----------------
__global__ void k_fin(const float* __restrict__ W2, const float* __restrict__ b2,
                      float* __restrict__ out) {
    int c = threadIdx.x;
    float acc = 0.f;
    #pragma unroll
    for (int k = 0; k < 64; k++)
        acc = fmaf(g_v[k], __ldg(&W2[k * 32 + c]), acc);
    float p = acc * (1.0f / (float)N_NODES) + b2[c];
    float m = p;
    #pragma unroll
    for (int o = 16; o; o >>= 1) m = fmaxf(m, __shfl_xor_sync(FULLM, m, o));
    float e = expf(p - m);
    float s = e;
    #pragma unroll
    for (int o = 16; o; o >>= 1) s += __shfl_xor_sync(FULLM, s, o);
    out[c] = p - m - logf(s);
}

// ---------------- launcher ----------------
extern "C" void kernel_launch(void* const* d_in, const int* in_sizes, int n_in,
                              void* d_out, int out_size) {
    const float* x  = (const float*)d_in[0];
    const void*  ei = d_in[1];
    const float* W1 = (const float*)d_in[2];
    const float* b1 = (const float*)d_in[3];
    const float* W2 = (const float*)d_in[4];
    const float* b2 = (const float*)d_in[5];
    float*       out = (float*)d_out;

    k_zero<<<(N_NODES + 255) / 256, 256>>>((const unsigned int*)ei);
    k_count<<<(N_EDGES + 255) / 256, 256>>>(ei);
    k_scan_partial<<<NCHUNK, 256>>>();
    k_scan_bsum<<<1, 32>>>();
    k_scan_add<<<(N_NODES + 255) / 256, 256>>>();
    k_place<<<(N_EDGES + 255) / 256, 256>>>(ei);

    k_gemm1<<<(N_NODES + 127) / 128, 256>>>(x, W1);
    k_agg1<<<NPART, 256>>>(b1);
    k_fin<<<1, 32>>>(W2, b2, out);
}

// round 10
// speedup vs baseline: 1.1668x; 1.1668x over previous
#include <cuda_runtime.h>
#include <cuda_fp16.h>

#define N_NODES 100000
#define N_EDGES 1600000
#define F_HID 64
#define NCHUNK ((N_NODES + 1023) / 1024)
#define NPART 12500                       // agg1 grid (= N_NODES/8 warps)
#define FULLM 0xffffffffu

// ---------------- scratch (static device globals) ----------------
__device__ int    g_is64;
__device__ int    g_cnt[N_NODES];
__device__ int    g_rowstart[N_NODES];
__device__ int    g_cursor[N_NODES];
__device__ int    g_col[N_EDGES];
__device__ int    g_bsum[NCHUNK];
__device__ float  g_dinv[N_NODES];
__device__ float  g_w[N_NODES];           // sum over out-edges of dinv[dst]
__device__ __half g_xsh[(size_t)N_NODES * F_HID];
__device__ float  g_partial[F_HID * NPART];
__device__ float  g_v[F_HID];

// ---------------- zero + dtype sniff (block 0) ----------------
__global__ void k_zero(const unsigned int* __restrict__ e) {
    int i = blockIdx.x * blockDim.x + threadIdx.x;
    if (i < N_NODES) { g_cnt[i] = 0; g_w[i] = 0.f; }
    if (blockIdx.x == 0 && threadIdx.x < 32) {
        unsigned int acc = 0;
        for (int k = threadIdx.x; k < 2048; k += 32)
            if (k & 1) acc |= e[k];
        #pragma unroll
        for (int o = 16; o; o >>= 1) acc |= __shfl_xor_sync(FULLM, acc, o);
        if (threadIdx.x == 0) g_is64 = (acc == 0u) ? 1 : 0;
    }
}

// ---------------- degree count over dst ----------------
__global__ void k_count(const void* __restrict__ eiv) {
    int e = blockIdx.x * blockDim.x + threadIdx.x;
    if (e >= N_EDGES) return;
    int d;
    if (g_is64) d = (int)((const long long*)eiv)[N_EDGES + e];
    else        d = ((const int*)eiv)[N_EDGES + e];
    atomicAdd(&g_cnt[d], 1);
}

// ---------------- exclusive scan, block partials ----------------
__global__ void k_scan_partial() {
    __shared__ int wsum[8];
    int t = threadIdx.x;
    int lane = t & 31, w = t >> 5;
    int gi = blockIdx.x * 256 + t;
    int4 v = make_int4(0, 0, 0, 0);
    if (gi < N_NODES / 4) v = ((const int4*)g_cnt)[gi];
    int p0 = v.x, p1 = p0 + v.y, p2 = p1 + v.z, p3 = p2 + v.w;
    int tsum = p3;
    int incl = tsum;
    #pragma unroll
    for (int o = 1; o < 32; o <<= 1) {
        int n = __shfl_up_sync(FULLM, incl, o);
        if (lane >= o) incl += n;
    }
    if (lane == 31) wsum[w] = incl;
    __syncthreads();
    if (w == 0) {
        int s = (lane < 8) ? wsum[lane] : 0;
        #pragma unroll
        for (int o = 1; o < 8; o <<= 1) {
            int n = __shfl_up_sync(FULLM, s, o);
            if (lane >= o) s += n;
        }
        if (lane < 8) wsum[lane] = s;
    }
    __syncthreads();
    int base = (w > 0 ? wsum[w - 1] : 0) + (incl - tsum);
    if (gi < N_NODES / 4)
        ((int4*)g_rowstart)[gi] = make_int4(base, base + p0, base + p1, base + p2);
    if (t == 0) g_bsum[blockIdx.x] = wsum[7];
}

// ---------------- scan finalize: in-block chunk-prefix (bsum fused) ------
__global__ void k_scan_add() {
    __shared__ int pref;
    int c = blockIdx.x >> 2;              // chunk id: 1024 nodes/chunk, 4 blocks/chunk
    int t = threadIdx.x;
    if (t < 32) {
        int s = 0;
        for (int j = t; j < NCHUNK; j += 32)
            if (j < c) s += g_bsum[j];
        #pragma unroll
        for (int o = 16; o; o >>= 1) s += __shfl_xor_sync(FULLM, s, o);
        if (t == 0) pref = s;
    }
    __syncthreads();
    int i = blockIdx.x * 256 + t;
    if (i < N_NODES) {
        int rs = g_rowstart[i] + pref;
        g_rowstart[i] = rs;
        g_cursor[i]   = rs;
        g_dinv[i] = rsqrtf((float)(g_cnt[i] + 1));
    }
}

// ---------------- CSR placement + w scatter ----------------
__global__ void k_place(const void* __restrict__ eiv) {
    int e = blockIdx.x * blockDim.x + threadIdx.x;
    if (e >= N_EDGES) return;
    int s, d;
    if (g_is64) {
        s = (int)((const long long*)eiv)[e];
        d = (int)((const long long*)eiv)[N_EDGES + e];
    } else {
        s = ((const int*)eiv)[e];
        d = ((const int*)eiv)[N_EDGES + e];
    }
    int pos = atomicAdd(&g_cursor[d], 1);
    g_col[pos] = s;
    atomicAdd(&g_w[s], g_dinv[d]);
}

// ---------------- GEMM1: xsh = fp16(dinv*(x@W1))  (R8-proven version) ----
// tile 32 rows x 64 cols; thread: 2 rows x 4 cols. N_NODES%32==0.
__global__ void k_gemm1(const float* __restrict__ x, const float* __restrict__ W1) {
    __shared__ float Ws[64 * 64];
    __shared__ float Xs[32][64];
    int t = threadIdx.x;
    for (int i = t; i < 64 * 64; i += 256) Ws[i] = W1[i];
    int c4 = t & 15;           // cols 4*c4 .. 4*c4+3
    int r  = t >> 4;           // rows r, r+16
    int ntiles = N_NODES / 32;
    for (int tile = blockIdx.x; tile < ntiles; tile += gridDim.x) {
        int row0 = tile * 32;
        const float4* xr = (const float4*)(x + (size_t)row0 * 64);
        __syncthreads();
        #pragma unroll
        for (int i = t; i < 512; i += 256) {
            int rr = i >> 4, qq = i & 15;
            ((float4*)&Xs[rr][0])[qq] = xr[rr * 16 + qq];
        }
        __syncthreads();
        float a0[4] = {0, 0, 0, 0}, a1[4] = {0, 0, 0, 0};
        #pragma unroll
        for (int k = 0; k < 64; k++) {
            float xa = Xs[r][k], xb = Xs[r + 16][k];
            float4 wv = ((const float4*)&Ws[k * 64])[c4];
            a0[0] = fmaf(xa, wv.x, a0[0]); a0[1] = fmaf(xa, wv.y, a0[1]);
            a0[2] = fmaf(xa, wv.z, a0[2]); a0[3] = fmaf(xa, wv.w, a0[3]);
            a1[0] = fmaf(xb, wv.x, a1[0]); a1[1] = fmaf(xb, wv.y, a1[1]);
            a1[2] = fmaf(xb, wv.z, a1[2]); a1[3] = fmaf(xb, wv.w, a1[3]);
        }
        int rowA = row0 + r, rowB = row0 + r + 16;
        float da = g_dinv[rowA], db = g_dinv[rowB];
        __half2* oa = (__half2*)(g_xsh + (size_t)rowA * 64);
        __half2* ob = (__half2*)(g_xsh + (size_t)rowB * 64);
        oa[2 * c4]     = __floats2half2_rn(da * a0[0], da * a0[1]);
        oa[2 * c4 + 1] = __floats2half2_rn(da * a0[2], da * a0[3]);
        ob[2 * c4]     = __floats2half2_rn(db * a1[0], db * a1[1]);
        ob[2 * c4 + 1] = __floats2half2_rn(db * a1[2], db * a1[3]);
    }
}

// ---------------- fused agg1 + relu + weighted pool (partial buffer) -----
__global__ void __launch_bounds__(256) k_agg1(const float* __restrict__ b1) {
    __shared__ float sp[8][64];
    int t = threadIdx.x;
    int warp = t >> 5, lane = t & 31;
    int gw = blockIdx.x * 8 + warp;       // all gw < N_NODES
    const __half2* xs2 = (const __half2*)g_xsh;
    int start = g_rowstart[gw];
    int cnt   = g_cnt[gw];
    float2 self = __half22float2(xs2[(size_t)gw * 32 + lane]);
    float ax = self.x, ay = self.y;
    float bx = 0.f, by = 0.f;
    for (int base = 0; base < cnt; base += 32) {
        int idx = base + lane;
        int j = (idx < cnt) ? g_col[start + idx] : 0;
        int m = min(32, cnt - base);
        int k = 0;
        for (; k + 8 <= m; k += 8) {
            int j0 = __shfl_sync(FULLM, j, k);
            int j1 = __shfl_sync(FULLM, j, k + 1);
            int j2 = __shfl_sync(FULLM, j, k + 2);
            int j3 = __shfl_sync(FULLM, j, k + 3);
            int j4 = __shfl_sync(FULLM, j, k + 4);
            int j5 = __shfl_sync(FULLM, j, k + 5);
            int j6 = __shfl_sync(FULLM, j, k + 6);
            int j7 = __shfl_sync(FULLM, j, k + 7);
            float2 v0 = __half22float2(__ldg(&xs2[(size_t)j0 * 32 + lane]));
            float2 v1 = __half22float2(__ldg(&xs2[(size_t)j1 * 32 + lane]));
            float2 v2 = __half22float2(__ldg(&xs2[(size_t)j2 * 32 + lane]));
            float2 v3 = __half22float2(__ldg(&xs2[(size_t)j3 * 32 + lane]));
            float2 v4 = __half22float2(__ldg(&xs2[(size_t)j4 * 32 + lane]));
            float2 v5 = __half22float2(__ldg(&xs2[(size_t)j5 * 32 + lane]));
            float2 v6 = __half22float2(__ldg(&xs2[(size_t)j6 * 32 + lane]));
            float2 v7 = __half22float2(__ldg(&xs2[(size_t)j7 * 32 + lane]));
            ax += (v0.x + v1.x) + (v2.x + v3.x);
            bx += (v4.x + v5.x) + (v6.x + v7.x);
            ay += (v0.y + v1.y) + (v2.y + v3.y);
            by += (v4.y + v5.y) + (v6.y + v7.y);
        }
        for (; k + 2 <= m; k += 2) {
            int ja = __shfl_sync(FULLM, j, k);
            int jb = __shfl_sync(FULLM, j, k + 1);
            float2 va = __half22float2(__ldg(&xs2[(size_t)ja * 32 + lane]));
            float2 vb = __half22float2(__ldg(&xs2[(size_t)jb * 32 + lane]));
            ax += va.x + vb.x; ay += va.y + vb.y;
        }
        for (; k < m; k++) {
            int jj = __shfl_sync(FULLM, j, k);
            float2 v = __half22float2(__ldg(&xs2[(size_t)jj * 32 + lane]));
            ax += v.x; ay += v.y;
        }
    }
    ax += bx; ay += by;
    float di = g_dinv[gw];
    float h0 = fmaxf(fmaf(di, ax, b1[2 * lane]),     0.f);
    float h1 = fmaxf(fmaf(di, ay, b1[2 * lane + 1]), 0.f);
    float coef = di * (di + g_w[gw]);
    sp[warp][2 * lane]     = coef * h0;
    sp[warp][2 * lane + 1] = coef * h1;
    __syncthreads();
    if (t < 64) {
        float s = 0.f;
        #pragma unroll
        for (int w = 0; w < 8; w++) s += sp[w][t];
        g_partial[(size_t)t * NPART + blockIdx.x] = s;
    }
}

// ---------------- reduce partials ----------------
__global__ void k_vred() {
    __shared__ float sh[8];
    int f = blockIdx.x, t = threadIdx.x;
    int lane = t & 31, w = t >> 5;
    float s = 0.f;
    for (int i = t; i < NPART; i += 256) s += g_partial[(size_t)f * NPART + i];
    #pragma unroll
    for (int o = 16; o; o >>= 1) s += __shfl_xor_sync(FULLM, s, o);
    if (lane == 0) sh[w] = s;
    __syncthreads();
    if (t == 0) {
        float tot = 0.f;
        #pragma unroll
        for (int i = 0; i < 8; i++) tot += sh[i];
        g_v[f] = tot;
    }
}

// ---------------- final: pooled = v@W2/N + b2, log_softmax ----------------
__global__ void k_fin(const float* __restrict__ W2, const float* __restrict__ b2,
                      float* __restrict__ out) {
    int c = threadIdx.x;
    float acc = 0.f;
    #pragma unroll
    for (int k = 0; k < 64; k++)
        acc = fmaf(g_v[k], __ldg(&W2[k * 32 + c]), acc);
    float p = acc * (1.0f / (float)N_NODES) + b2[c];
    float m = p;
    #pragma unroll
    for (int o = 16; o; o >>= 1) m = fmaxf(m, __shfl_xor_sync(FULLM, m, o));
    float e = expf(p - m);
    float s = e;
    #pragma unroll
    for (int o = 16; o; o >>= 1) s += __shfl_xor_sync(FULLM, s, o);
    out[c] = p - m - logf(s);
}

// ---------------- launcher ----------------
extern "C" void kernel_launch(void* const* d_in, const int* in_sizes, int n_in,
                              void* d_out, int out_size) {
    const float* x  = (const float*)d_in[0];
    const void*  ei = d_in[1];
    const float* W1 = (const float*)d_in[2];
    const float* b1 = (const float*)d_in[3];
    const float* W2 = (const float*)d_in[4];
    const float* b2 = (const float*)d_in[5];
    float*       out = (float*)d_out;

    k_zero<<<(N_NODES + 255) / 256, 256>>>((const unsigned int*)ei);
    k_count<<<(N_EDGES + 255) / 256, 256>>>(ei);
    k_scan_partial<<<NCHUNK, 256>>>();
    k_scan_add<<<(N_NODES + 255) / 256, 256>>>();
    k_place<<<(N_EDGES + 255) / 256, 256>>>(ei);

    k_gemm1<<<N_NODES / 32, 256>>>(x, W1);
    k_agg1<<<NPART, 256>>>(b1);
    k_vred<<<F_HID, 256>>>();
    k_fin<<<1, 32>>>(W2, b2, out);
}

// round 11
// speedup vs baseline: 1.2047x; 1.0325x over previous
#include <cuda_runtime.h>
#include <cuda_fp16.h>

#define N_NODES 100000
#define N_EDGES 1600000
#define F_HID 64
#define NCHUNK ((N_NODES + 1023) / 1024)
#define NPART 12500                       // agg1 grid (= N_NODES/8 warps)
#define FULLM 0xffffffffu

// ---------------- scratch (static device globals) ----------------
__device__ int    g_is64;
__device__ int    g_cnt[N_NODES];
__device__ int    g_rowstart[N_NODES];
__device__ int    g_cursor[N_NODES];
__device__ int    g_col[N_EDGES];
__device__ int    g_bsum[NCHUNK];
__device__ float  g_dinv[N_NODES];
__device__ float  g_w[N_NODES];           // sum over out-edges of dinv[dst]
__device__ __half g_xsh[(size_t)N_NODES * F_HID];
__device__ float  g_partial[F_HID * NPART];
__device__ float  g_v[F_HID];

// ---------------- zero + dtype sniff (block 0) ----------------
__global__ void k_zero(const unsigned int* __restrict__ e) {
    int i = blockIdx.x * blockDim.x + threadIdx.x;
    if (i < N_NODES) { g_cnt[i] = 0; g_w[i] = 0.f; }
    if (blockIdx.x == 0 && threadIdx.x < 32) {
        unsigned int acc = 0;
        for (int k = threadIdx.x; k < 2048; k += 32)
            if (k & 1) acc |= e[k];
        #pragma unroll
        for (int o = 16; o; o >>= 1) acc |= __shfl_xor_sync(FULLM, acc, o);
        if (threadIdx.x == 0) g_is64 = (acc == 0u) ? 1 : 0;
    }
}

// ---------------- degree count over dst ----------------
__global__ void k_count(const void* __restrict__ eiv) {
    int e = blockIdx.x * blockDim.x + threadIdx.x;
    if (e >= N_EDGES) return;
    int d;
    if (g_is64) d = (int)((const long long*)eiv)[N_EDGES + e];
    else        d = ((const int*)eiv)[N_EDGES + e];
    atomicAdd(&g_cnt[d], 1);
}

// ---------------- exclusive scan, block partials ----------------
__global__ void k_scan_partial() {
    __shared__ int wsum[8];
    int t = threadIdx.x;
    int lane = t & 31, w = t >> 5;
    int gi = blockIdx.x * 256 + t;
    int4 v = make_int4(0, 0, 0, 0);
    if (gi < N_NODES / 4) v = ((const int4*)g_cnt)[gi];
    int p0 = v.x, p1 = p0 + v.y, p2 = p1 + v.z, p3 = p2 + v.w;
    int tsum = p3;
    int incl = tsum;
    #pragma unroll
    for (int o = 1; o < 32; o <<= 1) {
        int n = __shfl_up_sync(FULLM, incl, o);
        if (lane >= o) incl += n;
    }
    if (lane == 31) wsum[w] = incl;
    __syncthreads();
    if (w == 0) {
        int s = (lane < 8) ? wsum[lane] : 0;
        #pragma unroll
        for (int o = 1; o < 8; o <<= 1) {
            int n = __shfl_up_sync(FULLM, s, o);
            if (lane >= o) s += n;
        }
        if (lane < 8) wsum[lane] = s;
    }
    __syncthreads();
    int base = (w > 0 ? wsum[w - 1] : 0) + (incl - tsum);
    if (gi < N_NODES / 4)
        ((int4*)g_rowstart)[gi] = make_int4(base, base + p0, base + p1, base + p2);
    if (t == 0) g_bsum[blockIdx.x] = wsum[7];
}

// ---------------- scan finalize: in-block chunk-prefix ----------------
__global__ void k_scan_add() {
    __shared__ int pref;
    int c = blockIdx.x >> 2;              // chunk id: 1024 nodes/chunk
    int t = threadIdx.x;
    if (t < 32) {
        int s = 0;
        for (int j = t; j < NCHUNK; j += 32)
            if (j < c) s += g_bsum[j];
        #pragma unroll
        for (int o = 16; o; o >>= 1) s += __shfl_xor_sync(FULLM, s, o);
        if (t == 0) pref = s;
    }
    __syncthreads();
    int i = blockIdx.x * 256 + t;
    if (i < N_NODES) {
        int rs = g_rowstart[i] + pref;
        g_rowstart[i] = rs;
        g_cursor[i]   = rs;
        g_dinv[i] = rsqrtf((float)(g_cnt[i] + 1));
    }
}

// ---------------- CSR placement + w scatter ----------------
__global__ void k_place(const void* __restrict__ eiv) {
    int e = blockIdx.x * blockDim.x + threadIdx.x;
    if (e >= N_EDGES) return;
    int s, d;
    if (g_is64) {
        s = (int)((const long long*)eiv)[e];
        d = (int)((const long long*)eiv)[N_EDGES + e];
    } else {
        s = ((const int*)eiv)[e];
        d = ((const int*)eiv)[N_EDGES + e];
    }
    int pos = atomicAdd(&g_cursor[d], 1);
    g_col[pos] = s;
    atomicAdd(&g_w[s], g_dinv[d]);
}

// ---------------- GEMM1: xsh = fp16(dinv*(x@W1))  (R8-proven) -----------
__global__ void k_gemm1(const float* __restrict__ x, const float* __restrict__ W1) {
    __shared__ float Ws[64 * 64];
    __shared__ float Xs[32][64];
    int t = threadIdx.x;
    for (int i = t; i < 64 * 64; i += 256) Ws[i] = W1[i];
    int c4 = t & 15;
    int r  = t >> 4;
    int ntiles = N_NODES / 32;
    for (int tile = blockIdx.x; tile < ntiles; tile += gridDim.x) {
        int row0 = tile * 32;
        const float4* xr = (const float4*)(x + (size_t)row0 * 64);
        __syncthreads();
        #pragma unroll
        for (int i = t; i < 512; i += 256) {
            int rr = i >> 4, qq = i & 15;
            ((float4*)&Xs[rr][0])[qq] = xr[rr * 16 + qq];
        }
        __syncthreads();
        float a0[4] = {0, 0, 0, 0}, a1[4] = {0, 0, 0, 0};
        #pragma unroll
        for (int k = 0; k < 64; k++) {
            float xa = Xs[r][k], xb = Xs[r + 16][k];
            float4 wv = ((const float4*)&Ws[k * 64])[c4];
            a0[0] = fmaf(xa, wv.x, a0[0]); a0[1] = fmaf(xa, wv.y, a0[1]);
            a0[2] = fmaf(xa, wv.z, a0[2]); a0[3] = fmaf(xa, wv.w, a0[3]);
            a1[0] = fmaf(xb, wv.x, a1[0]); a1[1] = fmaf(xb, wv.y, a1[1]);
            a1[2] = fmaf(xb, wv.z, a1[2]); a1[3] = fmaf(xb, wv.w, a1[3]);
        }
        int rowA = row0 + r, rowB = row0 + r + 16;
        float da = g_dinv[rowA], db = g_dinv[rowB];
        __half2* oa = (__half2*)(g_xsh + (size_t)rowA * 64);
        __half2* ob = (__half2*)(g_xsh + (size_t)rowB * 64);
        oa[2 * c4]     = __floats2half2_rn(da * a0[0], da * a0[1]);
        oa[2 * c4 + 1] = __floats2half2_rn(da * a0[2], da * a0[3]);
        ob[2 * c4]     = __floats2half2_rn(db * a1[0], db * a1[1]);
        ob[2 * c4 + 1] = __floats2half2_rn(db * a1[2], db * a1[3]);
    }
}

// ---------------- fused agg1: 2 neighbors/iter, half2 accumulation -------
// lane = (parity, feature-quad): half = lane>>4 picks even/odd neighbor,
// fl = lane&15 picks features 4*fl..4*fl+3 (one uint2 = 2 half2).
__global__ void __launch_bounds__(256) k_agg1(const float* __restrict__ b1) {
    __shared__ float sp[8][64];
    int t = threadIdx.x;
    int warp = t >> 5, lane = t & 31;
    int gw = blockIdx.x * 8 + warp;       // all gw < N_NODES
    const uint2* xs4 = (const uint2*)g_xsh;   // 16 uint2 per row
    int start = g_rowstart[gw];
    int cnt   = g_cnt[gw];
    int half  = lane >> 4;
    int fl    = lane & 15;
    __half2 acc0 = __float2half2_rn(0.f), acc1 = acc0;
    if (half == 0) {                       // self loop into even-partial
        uint2 s = xs4[(size_t)gw * 16 + fl];
        acc0 = *(__half2*)&s.x; acc1 = *(__half2*)&s.y;
    }
    for (int base = 0; base < cnt; base += 32) {
        int idx = base + lane;
        int jreg = (idx < cnt) ? g_col[start + idx] : 0;
        int m = min(32, cnt - base);
        int kp = 0;
        for (; kp + 8 <= m; kp += 8) {     // 4 pair-iters, independent loads
            int j0 = __shfl_sync(FULLM, jreg, kp     + half);
            int j1 = __shfl_sync(FULLM, jreg, kp + 2 + half);
            int j2 = __shfl_sync(FULLM, jreg, kp + 4 + half);
            int j3 = __shfl_sync(FULLM, jreg, kp + 6 + half);
            uint2 v0 = __ldg(&xs4[(size_t)j0 * 16 + fl]);
            uint2 v1 = __ldg(&xs4[(size_t)j1 * 16 + fl]);
            uint2 v2 = __ldg(&xs4[(size_t)j2 * 16 + fl]);
            uint2 v3 = __ldg(&xs4[(size_t)j3 * 16 + fl]);
            acc0 = __hadd2(acc0, __hadd2(__hadd2(*(__half2*)&v0.x, *(__half2*)&v1.x),
                                         __hadd2(*(__half2*)&v2.x, *(__half2*)&v3.x)));
            acc1 = __hadd2(acc1, __hadd2(__hadd2(*(__half2*)&v0.y, *(__half2*)&v1.y),
                                         __hadd2(*(__half2*)&v2.y, *(__half2*)&v3.y)));
        }
        for (; kp + 2 <= m; kp += 2) {
            int j = __shfl_sync(FULLM, jreg, kp + half);
            uint2 v = __ldg(&xs4[(size_t)j * 16 + fl]);
            acc0 = __hadd2(acc0, *(__half2*)&v.x);
            acc1 = __hadd2(acc1, *(__half2*)&v.y);
        }
        if (kp < m) {                      // odd tail: even-group only
            int j = __shfl_sync(FULLM, jreg, kp);
            if (half == 0) {
                uint2 v = __ldg(&xs4[(size_t)j * 16 + fl]);
                acc0 = __hadd2(acc0, *(__half2*)&v.x);
                acc1 = __hadd2(acc1, *(__half2*)&v.y);
            }
        }
    }
    // combine even/odd partials across the two 16-lane groups
    unsigned int u0 = *(unsigned int*)&acc0;
    unsigned int u1 = *(unsigned int*)&acc1;
    unsigned int p0 = __shfl_xor_sync(FULLM, u0, 16);
    unsigned int p1 = __shfl_xor_sync(FULLM, u1, 16);
    acc0 = __hadd2(acc0, *(__half2*)&p0);
    acc1 = __hadd2(acc1, *(__half2*)&p1);
    if (half == 0) {
        float2 f01 = __half22float2(acc0);
        float2 f23 = __half22float2(acc1);
        float di = g_dinv[gw];
        float coef = di * (di + g_w[gw]);
        int f = 4 * fl;
        float4 o;
        o.x = coef * fmaxf(fmaf(di, f01.x, b1[f]),     0.f);
        o.y = coef * fmaxf(fmaf(di, f01.y, b1[f + 1]), 0.f);
        o.z = coef * fmaxf(fmaf(di, f23.x, b1[f + 2]), 0.f);
        o.w = coef * fmaxf(fmaf(di, f23.y, b1[f + 3]), 0.f);
        *(float4*)&sp[warp][f] = o;
    }
    __syncthreads();
    if (t < 64) {
        float s = 0.f;
        #pragma unroll
        for (int w = 0; w < 8; w++) s += sp[w][t];
        g_partial[(size_t)t * NPART + blockIdx.x] = s;
    }
}

// ---------------- reduce partials ----------------
__global__ void k_vred() {
    __shared__ float sh[8];
    int f = blockIdx.x, t = threadIdx.x;
    int lane = t & 31, w = t >> 5;
    float s = 0.f;
    for (int i = t; i < NPART; i += 256) s += g_partial[(size_t)f * NPART + i];
    #pragma unroll
    for (int o = 16; o; o >>= 1) s += __shfl_xor_sync(FULLM, s, o);
    if (lane == 0) sh[w] = s;
    __syncthreads();
    if (t == 0) {
        float tot = 0.f;
        #pragma unroll
        for (int i = 0; i < 8; i++) tot += sh[i];
        g_v[f] = tot;
    }
}

// ---------------- final: pooled = v@W2/N + b2, log_softmax ----------------
__global__ void k_fin(const float* __restrict__ W2, const float* __restrict__ b2,
                      float* __restrict__ out) {
    int c = threadIdx.x;
    float acc = 0.f;
    #pragma unroll
    for (int k = 0; k < 64; k++)
        acc = fmaf(g_v[k], __ldg(&W2[k * 32 + c]), acc);
    float p = acc * (1.0f / (float)N_NODES) + b2[c];
    float m = p;
    #pragma unroll
    for (int o = 16; o; o >>= 1) m = fmaxf(m, __shfl_xor_sync(FULLM, m, o));
    float e = expf(p - m);
    float s = e;
    #pragma unroll
    for (int o = 16; o; o >>= 1) s += __shfl_xor_sync(FULLM, s, o);
    out[c] = p - m - logf(s);
}

// ---------------- launcher ----------------
extern "C" void kernel_launch(void* const* d_in, const int* in_sizes, int n_in,
                              void* d_out, int out_size) {
    const float* x  = (const float*)d_in[0];
    const void*  ei = d_in[1];
    const float* W1 = (const float*)d_in[2];
    const float* b1 = (const float*)d_in[3];
    const float* W2 = (const float*)d_in[4];
    const float* b2 = (const float*)d_in[5];
    float*       out = (float*)d_out;

    k_zero<<<(N_NODES + 255) / 256, 256>>>((const unsigned int*)ei);
    k_count<<<(N_EDGES + 255) / 256, 256>>>(ei);
    k_scan_partial<<<NCHUNK, 256>>>();
    k_scan_add<<<(N_NODES + 255) / 256, 256>>>();
    k_place<<<(N_EDGES + 255) / 256, 256>>>(ei);

    k_gemm1<<<N_NODES / 32, 256>>>(x, W1);
    k_agg1<<<NPART, 256>>>(b1);
    k_vred<<<F_HID, 256>>>();
    k_fin<<<1, 32>>>(W2, b2, out);
}

// round 13
// speedup vs baseline: 1.4501x; 1.2037x over previous
#include <cuda_runtime.h>
#include <cuda_fp16.h>

#define N_NODES 100000
#define N_EDGES 1600000
#define F_HID 64
#define NCHUNK ((N_NODES + 1023) / 1024)
#define NPART 12500                       // agg1 grid (= N_NODES/8 warps)
#define FULLM 0xffffffffu

// ---------------- scratch (static device globals) ----------------
__device__ int    g_is64;
__device__ int    g_cnt[N_NODES];
__device__ int    g_rowstart[N_NODES];
__device__ int    g_cursor[N_NODES];
__device__ int    g_col[N_EDGES];
__device__ int    g_bsum[NCHUNK];
__device__ float  g_dinv[N_NODES];
__device__ float  g_w[N_NODES];           // sum over out-edges of dinv[dst]
__device__ __half g_xsh[(size_t)N_NODES * F_HID];
__device__ float  g_partial[F_HID * NPART];
__device__ float  g_v[F_HID];

__device__ __forceinline__ float tf32r(float f) {
    asm("cvt.rna.tf32.f32 %0, %0;" : "+f"(f));
    return f;
}

// ---------------- zero + dtype sniff (block 0) ----------------
__global__ void k_zero(const unsigned int* __restrict__ e) {
    int i = blockIdx.x * blockDim.x + threadIdx.x;
    if (i < N_NODES) { g_cnt[i] = 0; g_w[i] = 0.f; }
    if (blockIdx.x == 0 && threadIdx.x < 32) {
        unsigned int acc = 0;
        for (int k = threadIdx.x; k < 2048; k += 32)
            if (k & 1) acc |= e[k];
        #pragma unroll
        for (int o = 16; o; o >>= 1) acc |= __shfl_xor_sync(FULLM, acc, o);
        if (threadIdx.x == 0) g_is64 = (acc == 0u) ? 1 : 0;
    }
}

// ---------------- degree count over dst (low-word reads) ----------------
__global__ void k_count(const void* __restrict__ eiv) {
    int e = blockIdx.x * blockDim.x + threadIdx.x;
    if (e >= N_EDGES) return;
    const int* ei = (const int*)eiv;
    int d;
    if (g_is64) d = ei[2 * ((size_t)N_EDGES + e)];   // little-endian low word
    else        d = ei[(size_t)N_EDGES + e];
    atomicAdd(&g_cnt[d], 1);
}

// ---------------- exclusive scan, block partials ----------------
__global__ void k_scan_partial() {
    __shared__ int wsum[8];
    int t = threadIdx.x;
    int lane = t & 31, w = t >> 5;
    int gi = blockIdx.x * 256 + t;
    int4 v = make_int4(0, 0, 0, 0);
    if (gi < N_NODES / 4) v = ((const int4*)g_cnt)[gi];
    int p0 = v.x, p1 = p0 + v.y, p2 = p1 + v.z, p3 = p2 + v.w;
    int tsum = p3;
    int incl = tsum;
    #pragma unroll
    for (int o = 1; o < 32; o <<= 1) {
        int n = __shfl_up_sync(FULLM, incl, o);
        if (lane >= o) incl += n;
    }
    if (lane == 31) wsum[w] = incl;
    __syncthreads();
    if (w == 0) {
        int s = (lane < 8) ? wsum[lane] : 0;
        #pragma unroll
        for (int o = 1; o < 8; o <<= 1) {
            int n = __shfl_up_sync(FULLM, s, o);
            if (lane >= o) s += n;
        }
        if (lane < 8) wsum[lane] = s;
    }
    __syncthreads();
    int base = (w > 0 ? wsum[w - 1] : 0) + (incl - tsum);
    if (gi < N_NODES / 4)
        ((int4*)g_rowstart)[gi] = make_int4(base, base + p0, base + p1, base + p2);
    if (t == 0) g_bsum[blockIdx.x] = wsum[7];
}

// ---------------- scan finalize: in-block chunk-prefix ----------------
__global__ void k_scan_add() {
    __shared__ int pref;
    int c = blockIdx.x >> 2;              // chunk id: 1024 nodes/chunk
    int t = threadIdx.x;
    if (t < 32) {
        int s = 0;
        for (int j = t; j < NCHUNK; j += 32)
            if (j < c) s += g_bsum[j];
        #pragma unroll
        for (int o = 16; o; o >>= 1) s += __shfl_xor_sync(FULLM, s, o);
        if (t == 0) pref = s;
    }
    __syncthreads();
    int i = blockIdx.x * 256 + t;
    if (i < N_NODES) {
        int rs = g_rowstart[i] + pref;
        g_rowstart[i] = rs;
        g_cursor[i]   = rs;
        g_dinv[i] = rsqrtf((float)(g_cnt[i] + 1));
    }
}

// ---------------- CSR placement + w scatter (low-word reads) -------------
__global__ void k_place(const void* __restrict__ eiv) {
    int e = blockIdx.x * blockDim.x + threadIdx.x;
    if (e >= N_EDGES) return;
    const int* ei = (const int*)eiv;
    int s, d;
    if (g_is64) {
        s = ei[2 * (size_t)e];
        d = ei[2 * ((size_t)N_EDGES + e)];
    } else {
        s = ei[(size_t)e];
        d = ei[(size_t)N_EDGES + e];
    }
    int pos = atomicAdd(&g_cursor[d], 1);
    g_col[pos] = s;
    atomicAdd(&g_w[s], g_dinv[d]);
}

// ---------------- GEMM1: xsh = fp16(dinv*(x@W1)) via tf32 mma.sync -------
// block tile 64 rows x 64 cols; 8 warps = 4 row-strips x 2 n-halves.
// warp: 8 k-steps x 4 n-tiles of m16n8k8.
__global__ void __launch_bounds__(256) k_gemm1(const float* __restrict__ x,
                                               const float* __restrict__ W1) {
    __shared__ float WsT[64][68];   // [n][k], tf32-rounded, padded
    __shared__ float Xs[64][68];    // [row][k], tf32-rounded, padded
    int t = threadIdx.x;
    int lane = t & 31, warp = t >> 5;
    int rs = warp & 3;              // row strip: rows 16*rs .. 16*rs+15
    int nh = warp >> 2;             // n half:   cols 32*nh .. 32*nh+31
    int g = lane >> 2, tig = lane & 3;
    // stage W transposed + rounded (once per block)
    for (int i = t; i < 1024; i += 256) {
        int k = i >> 4, n4 = (i & 15) * 4;
        float4 wv = *(const float4*)(W1 + k * 64 + n4);
        WsT[n4 + 0][k] = tf32r(wv.x);
        WsT[n4 + 1][k] = tf32r(wv.y);
        WsT[n4 + 2][k] = tf32r(wv.z);
        WsT[n4 + 3][k] = tf32r(wv.w);
    }
    int ntiles = (N_NODES + 63) / 64;
    for (int tile = blockIdx.x; tile < ntiles; tile += gridDim.x) {
        int row0 = tile * 64;
        __syncthreads();
        for (int i = t; i < 1024; i += 256) {   // 64 rows x 16 float4
            int rr = i >> 4, q = i & 15;
            int grow = row0 + rr;
            float4 v = make_float4(0.f, 0.f, 0.f, 0.f);
            if (grow < N_NODES) v = *(const float4*)(x + (size_t)grow * 64 + 4 * q);
            Xs[rr][4 * q + 0] = tf32r(v.x);
            Xs[rr][4 * q + 1] = tf32r(v.y);
            Xs[rr][4 * q + 2] = tf32r(v.z);
            Xs[rr][4 * q + 3] = tf32r(v.w);
        }
        __syncthreads();
        float acc[4][4] = {};
        #pragma unroll
        for (int k0 = 0; k0 < 8; k0++) {
            int kk = 8 * k0;
            unsigned int a0 = __float_as_uint(Xs[16 * rs + g][kk + tig]);
            unsigned int a1 = __float_as_uint(Xs[16 * rs + g + 8][kk + tig]);
            unsigned int a2 = __float_as_uint(Xs[16 * rs + g][kk + tig + 4]);
            unsigned int a3 = __float_as_uint(Xs[16 * rs + g + 8][kk + tig + 4]);
            #pragma unroll
            for (int n0 = 0; n0 < 4; n0++) {
                int nn = 32 * nh + 8 * n0;
                unsigned int b0 = __float_as_uint(WsT[nn + g][kk + tig]);
                unsigned int b1 = __float_as_uint(WsT[nn + g][kk + tig + 4]);
                asm("mma.sync.aligned.m16n8k8.row.col.f32.tf32.tf32.f32 "
                    "{%0,%1,%2,%3}, {%4,%5,%6,%7}, {%8,%9}, {%0,%1,%2,%3};"
                    : "+f"(acc[n0][0]), "+f"(acc[n0][1]),
                      "+f"(acc[n0][2]), "+f"(acc[n0][3])
                    : "r"(a0), "r"(a1), "r"(a2), "r"(a3), "r"(b0), "r"(b1));
            }
        }
        int rowA = row0 + 16 * rs + g;
        int rowB = rowA + 8;
        float da = (rowA < N_NODES) ? g_dinv[rowA] : 0.f;
        float db = (rowB < N_NODES) ? g_dinv[rowB] : 0.f;
        #pragma unroll
        for (int n0 = 0; n0 < 4; n0++) {
            int nn = 32 * nh + 8 * n0 + 2 * tig;
            if (rowA < N_NODES)
                *(__half2*)(g_xsh + (size_t)rowA * 64 + nn) =
                    __floats2half2_rn(da * acc[n0][0], da * acc[n0][1]);
            if (rowB < N_NODES)
                *(__half2*)(g_xsh + (size_t)rowB * 64 + nn) =
                    __floats2half2_rn(db * acc[n0][2], db * acc[n0][3]);
        }
    }
}

// ---------------- fused agg1: 2 neighbors/iter, half2 accumulation -------
__global__ void __launch_bounds__(256) k_agg1(const float* __restrict__ b1) {
    __shared__ float sp[8][64];
    int t = threadIdx.x;
    int warp = t >> 5, lane = t & 31;
    int gw = blockIdx.x * 8 + warp;       // all gw < N_NODES
    const uint2* xs4 = (const uint2*)g_xsh;   // 16 uint2 per row
    int start = g_rowstart[gw];
    int cnt   = g_cnt[gw];
    int half  = lane >> 4;
    int fl    = lane & 15;
    __half2 acc0 = __float2half2_rn(0.f), acc1 = acc0;
    if (half == 0) {                       // self loop into even-partial
        uint2 s = xs4[(size_t)gw * 16 + fl];
        acc0 = *(__half2*)&s.x; acc1 = *(__half2*)&s.y;
    }
    for (int base = 0; base < cnt; base += 32) {
        int idx = base + lane;
        int jreg = (idx < cnt) ? g_col[start + idx] : 0;
        int m = min(32, cnt - base);
        int kp = 0;
        for (; kp + 8 <= m; kp += 8) {
            int j0 = __shfl_sync(FULLM, jreg, kp     + half);
            int j1 = __shfl_sync(FULLM, jreg, kp + 2 + half);
            int j2 = __shfl_sync(FULLM, jreg, kp + 4 + half);
            int j3 = __shfl_sync(FULLM, jreg, kp + 6 + half);
            uint2 v0 = __ldg(&xs4[(size_t)j0 * 16 + fl]);
            uint2 v1 = __ldg(&xs4[(size_t)j1 * 16 + fl]);
            uint2 v2 = __ldg(&xs4[(size_t)j2 * 16 + fl]);
            uint2 v3 = __ldg(&xs4[(size_t)j3 * 16 + fl]);
            acc0 = __hadd2(acc0, __hadd2(__hadd2(*(__half2*)&v0.x, *(__half2*)&v1.x),
                                         __hadd2(*(__half2*)&v2.x, *(__half2*)&v3.x)));
            acc1 = __hadd2(acc1, __hadd2(__hadd2(*(__half2*)&v0.y, *(__half2*)&v1.y),
                                         __hadd2(*(__half2*)&v2.y, *(__half2*)&v3.y)));
        }
        for (; kp + 2 <= m; kp += 2) {
            int j = __shfl_sync(FULLM, jreg, kp + half);
            uint2 v = __ldg(&xs4[(size_t)j * 16 + fl]);
            acc0 = __hadd2(acc0, *(__half2*)&v.x);
            acc1 = __hadd2(acc1, *(__half2*)&v.y);
        }
        if (kp < m) {                      // odd tail: even-group only
            int j = __shfl_sync(FULLM, jreg, kp);
            if (half == 0) {
                uint2 v = __ldg(&xs4[(size_t)j * 16 + fl]);
                acc0 = __hadd2(acc0, *(__half2*)&v.x);
                acc1 = __hadd2(acc1, *(__half2*)&v.y);
            }
        }
    }
    unsigned int u0 = *(unsigned int*)&acc0;
    unsigned int u1 = *(unsigned int*)&acc1;
    unsigned int p0 = __shfl_xor_sync(FULLM, u0, 16);
    unsigned int p1 = __shfl_xor_sync(FULLM, u1, 16);
    acc0 = __hadd2(acc0, *(__half2*)&p0);
    acc1 = __hadd2(acc1, *(__half2*)&p1);
    if (half == 0) {
        float2 f01 = __half22float2(acc0);
        float2 f23 = __half22float2(acc1);
        float di = g_dinv[gw];
        float coef = di * (di + g_w[gw]);
        int f = 4 * fl;
        float4 o;
        o.x = coef * fmaxf(fmaf(di, f01.x, b1[f]),     0.f);
        o.y = coef * fmaxf(fmaf(di, f01.y, b1[f + 1]), 0.f);
        o.z = coef * fmaxf(fmaf(di, f23.x, b1[f + 2]), 0.f);
        o.w = coef * fmaxf(fmaf(di, f23.y, b1[f + 3]), 0.f);
        *(float4*)&sp[warp][f] = o;
    }
    __syncthreads();
    if (t < 64) {
        float s = 0.f;
        #pragma unroll
        for (int w = 0; w < 8; w++) s += sp[w][t];
        g_partial[(size_t)t * NPART + blockIdx.x] = s;
    }
}

// ---------------- reduce partials ----------------
__global__ void k_vred() {
    __shared__ float sh[8];
    int f = blockIdx.x, t = threadIdx.x;
    int lane = t & 31, w = t >> 5;
    float s = 0.f;
    for (int i = t; i < NPART; i += 256) s += g_partial[(size_t)f * NPART + i];
    #pragma unroll
    for (int o = 16; o; o >>= 1) s += __shfl_xor_sync(FULLM, s, o);
    if (lane == 0) sh[w] = s;
    __syncthreads();
    if (t == 0) {
        float tot = 0.f;
        #pragma unroll
        for (int i = 0; i < 8; i++) tot += sh[i];
        g_v[f] = tot;
    }
}

// ---------------- final: pooled = v@W2/N + b2, log_softmax ----------------
__global__ void k_fin(const float* __restrict__ W2, const float* __restrict__ b2,
                      float* __restrict__ out) {
    int c = threadIdx.x;
    float acc = 0.f;
    #pragma unroll
    for (int k = 0; k < 64; k++)
        acc = fmaf(g_v[k], __ldg(&W2[k * 32 + c]), acc);
    float p = acc * (1.0f / (float)N_NODES) + b2[c];
    float m = p;
    #pragma unroll
    for (int o = 16; o; o >>= 1) m = fmaxf(m, __shfl_xor_sync(FULLM, m, o));
    float e = expf(p - m);
    float s = e;
    #pragma unroll
    for (int o = 16; o; o >>= 1) s += __shfl_xor_sync(FULLM, s, o);
    out[c] = p - m - logf(s);
}

// ---------------- launcher ----------------
extern "C" void kernel_launch(void* const* d_in, const int* in_sizes, int n_in,
                              void* d_out, int out_size) {
    const float* x  = (const float*)d_in[0];
    const void*  ei = d_in[1];
    const float* W1 = (const float*)d_in[2];
    const float* b1 = (const float*)d_in[3];
    const float* W2 = (const float*)d_in[4];
    const float* b2 = (const float*)d_in[5];
    float*       out = (float*)d_out;

    k_zero<<<(N_NODES + 255) / 256, 256>>>((const unsigned int*)ei);
    k_count<<<(N_EDGES + 255) / 256, 256>>>(ei);
    k_scan_partial<<<NCHUNK, 256>>>();
    k_scan_add<<<(N_NODES + 255) / 256, 256>>>();
    k_place<<<(N_EDGES + 255) / 256, 256>>>(ei);

    k_gemm1<<<(N_NODES + 63) / 64, 256>>>(x, W1);
    k_agg1<<<NPART, 256>>>(b1);
    k_vred<<<F_HID, 256>>>();
    k_fin<<<1, 32>>>(W2, b2, out);
}